// round 2
// baseline (speedup 1.0000x reference)
#include <cuda_runtime.h>
#include <cstdint>

#define N_NODES 40000
#define N_EDGES 640000
#define N_GRAPHS 64
#define D 128
#define LN_EPS 1e-5f

// ---------------- scratch (no allocations allowed) ----------------
__device__ float g_h[(size_t)N_NODES * D];
__device__ float g_agg[(size_t)N_NODES * D];
__device__ float g_inv[N_NODES];

// ---------------- f32x2 packed helpers (Blackwell FFMA2) ----------------
__device__ __forceinline__ unsigned long long pack2(float lo, float hi) {
    unsigned long long r;
    asm("mov.b64 %0, {%1, %2};" : "=l"(r) : "f"(lo), "f"(hi));
    return r;
}
__device__ __forceinline__ float2 unpack2(unsigned long long v) {
    float2 r;
    asm("mov.b64 {%0, %1}, %2;" : "=f"(r.x), "=f"(r.y) : "l"(v));
    return r;
}
__device__ __forceinline__ void fma2(unsigned long long& d, unsigned long long a,
                                     unsigned long long b) {
    asm("fma.rn.f32x2 %0, %1, %2, %0;" : "+l"(d) : "l"(a), "l"(b));
}

// ---------------- tiny utility kernels ----------------
__global__ void zero_kernel(float4* p, int n4) {
    int i = blockIdx.x * blockDim.x + threadIdx.x;
    if (i < n4) p[i] = make_float4(0.f, 0.f, 0.f, 0.f);
}

__global__ void count_deg_kernel(const int* __restrict__ ei,
                                 float* __restrict__ deg) {
    int e = blockIdx.x * blockDim.x + threadIdx.x;
    if (e < N_EDGES) {
        int d = __ldg(ei + N_EDGES + e);
        atomicAdd(deg + d, 1.0f);
    }
}

__global__ void finalize_inv_kernel(float* inv) {
    int i = blockIdx.x * blockDim.x + threadIdx.x;
    if (i < N_NODES) inv[i] = 1.0f / fmaxf(inv[i], 1.0f);
}

// ---------------- edge scatter: agg[dst] += h[src], one warp per edge ----------------
__global__ __launch_bounds__(256) void scatter_kernel(
    const int* __restrict__ ei, const float* __restrict__ h,
    float* __restrict__ agg) {
    int gtid = blockIdx.x * blockDim.x + threadIdx.x;
    int e = gtid >> 5;
    int lane = gtid & 31;
    if (e >= N_EDGES) return;
    int s = __ldg(ei + e);
    int d = __ldg(ei + N_EDGES + e);
    float4 v = __ldg((const float4*)(h + (size_t)s * D) + lane);
    const float* p = agg + (size_t)d * D + lane * 4;
    asm volatile("red.global.add.v4.f32 [%0], {%1, %2, %3, %4};"
                 :: "l"(p), "f"(v.x), "f"(v.y), "f"(v.z), "f"(v.w)
                 : "memory");
}

// ---------------- fused GEMM ----------------
// out[r, :] = sum_seg (A_seg[r, :] * rowscale_seg) @ W_seg^T  + bias
// optionally LayerNorm(g, b) then ReLU. Tile: 128 rows x 128 cols, K in 16-chunks.
template <int NSEG, bool DO_LN, bool DO_RELU>
__global__ __launch_bounds__(256) void gemm_fused(
    const float* __restrict__ A0, const float* __restrict__ W0,
    const float* __restrict__ A1, const float* __restrict__ W1,
    const float* __restrict__ rowscale0,  // applied to segment 0 only (may be null)
    const float* __restrict__ bias,
    const float* __restrict__ lng, const float* __restrict__ lnb,
    float* __restrict__ out, int nrows) {
    __shared__ __align__(16) float As[16][132];
    __shared__ __align__(16) float Bs[16][132];
    __shared__ __align__(16) float red0[128][17];
    __shared__ __align__(16) float red1[128][17];
    __shared__ float s_mu[128];
    __shared__ float s_rs[128];

    const int tid = threadIdx.x;
    const int tx = tid & 15;
    const int ty = tid >> 4;
    const int row0 = blockIdx.x * 128;

    unsigned long long acc[8][4];
#pragma unroll
    for (int i = 0; i < 8; i++)
#pragma unroll
        for (int j = 0; j < 4; j++) acc[i][j] = 0ULL;

#pragma unroll
    for (int seg = 0; seg < NSEG; seg++) {
        const float* A = (seg == 0) ? A0 : A1;
        const float* W = (seg == 0) ? W0 : W1;
        const float* rsc = (seg == 0) ? rowscale0 : nullptr;
#pragma unroll 1
        for (int kb = 0; kb < D; kb += 16) {
            // stage A (128 rows x 16 k, transposed) and W (128 cols x 16 k, transposed)
#pragma unroll
            for (int it = 0; it < 2; it++) {
                int slot = tid + it * 256;   // 0..511
                int r = slot >> 2;           // 0..127
                int kq = slot & 3;           // 0..3
                int grow = row0 + r;
                float4 v = make_float4(0.f, 0.f, 0.f, 0.f);
                if (grow < nrows) {
                    v = __ldg((const float4*)(A + (size_t)grow * D + kb) + kq);
                    if (rsc) {
                        float sc = __ldg(rsc + grow);
                        v.x *= sc; v.y *= sc; v.z *= sc; v.w *= sc;
                    }
                }
                As[kq * 4 + 0][r] = v.x;
                As[kq * 4 + 1][r] = v.y;
                As[kq * 4 + 2][r] = v.z;
                As[kq * 4 + 3][r] = v.w;
                float4 w = __ldg((const float4*)(W + (size_t)r * D + kb) + kq);
                Bs[kq * 4 + 0][r] = w.x;
                Bs[kq * 4 + 1][r] = w.y;
                Bs[kq * 4 + 2][r] = w.z;
                Bs[kq * 4 + 3][r] = w.w;
            }
            __syncthreads();
#pragma unroll
            for (int k = 0; k < 16; k++) {
                const unsigned long long* pb =
                    (const unsigned long long*)&Bs[k][tx * 8];
                unsigned long long b0 = pb[0], b1 = pb[1], b2 = pb[2], b3 = pb[3];
#pragma unroll
                for (int i = 0; i < 8; i++) {
                    float a = As[k][ty * 8 + i];
                    unsigned long long a2 = pack2(a, a);
                    fma2(acc[i][0], a2, b0);
                    fma2(acc[i][1], a2, b1);
                    fma2(acc[i][2], a2, b2);
                    fma2(acc[i][3], a2, b3);
                }
            }
            __syncthreads();
        }
    }

    // ---------------- epilogue ----------------
    float o[8][8];
#pragma unroll
    for (int i = 0; i < 8; i++)
#pragma unroll
        for (int j = 0; j < 4; j++) {
            float2 f = unpack2(acc[i][j]);
            o[i][2 * j] = f.x;
            o[i][2 * j + 1] = f.y;
        }

    float bcol[8];
#pragma unroll
    for (int j = 0; j < 8; j++) bcol[j] = __ldg(bias + tx * 8 + j);
#pragma unroll
    for (int i = 0; i < 8; i++)
#pragma unroll
        for (int j = 0; j < 8; j++) o[i][j] += bcol[j];

    if (DO_LN) {
#pragma unroll
        for (int i = 0; i < 8; i++) {
            float s = 0.f, q = 0.f;
#pragma unroll
            for (int j = 0; j < 8; j++) {
                s += o[i][j];
                q += o[i][j] * o[i][j];
            }
            red0[ty * 8 + i][tx] = s;
            red1[ty * 8 + i][tx] = q;
        }
        __syncthreads();
        if (tid < 128) {
            float s = 0.f, q = 0.f;
#pragma unroll
            for (int t = 0; t < 16; t++) {
                s += red0[tid][t];
                q += red1[tid][t];
            }
            float mu = s * (1.0f / 128.0f);
            float var = q * (1.0f / 128.0f) - mu * mu;
            s_mu[tid] = mu;
            s_rs[tid] = rsqrtf(var + LN_EPS);
        }
        __syncthreads();
        float gj[8], bj[8];
#pragma unroll
        for (int j = 0; j < 8; j++) {
            gj[j] = __ldg(lng + tx * 8 + j);
            bj[j] = __ldg(lnb + tx * 8 + j);
        }
#pragma unroll
        for (int i = 0; i < 8; i++) {
            float mu = s_mu[ty * 8 + i];
            float rs = s_rs[ty * 8 + i];
#pragma unroll
            for (int j = 0; j < 8; j++)
                o[i][j] = (o[i][j] - mu) * rs * gj[j] + bj[j];
        }
    }

    if (DO_RELU) {
#pragma unroll
        for (int i = 0; i < 8; i++)
#pragma unroll
            for (int j = 0; j < 8; j++) o[i][j] = fmaxf(o[i][j], 0.f);
    }

#pragma unroll
    for (int i = 0; i < 8; i++) {
        int grow = row0 + ty * 8 + i;
        if (grow < nrows) {
            float4* po = (float4*)(out + (size_t)grow * D + tx * 8);
            po[0] = make_float4(o[i][0], o[i][1], o[i][2], o[i][3]);
            po[1] = make_float4(o[i][4], o[i][5], o[i][6], o[i][7]);
        }
    }
}

// ---------------- per-graph sum pool (batch is sorted -> no atomics) ----------------
__global__ void graph_pool_kernel(const float* __restrict__ node,
                                  const int* __restrict__ batch,
                                  float* __restrict__ out) {
    int g = blockIdx.x;
    int c = threadIdx.x;  // 0..127
    int lo = 0, hi = N_NODES;
    while (lo < hi) {
        int mid = (lo + hi) >> 1;
        if (__ldg(batch + mid) < g) lo = mid + 1; else hi = mid;
    }
    int start = lo;
    hi = N_NODES;
    while (lo < hi) {
        int mid = (lo + hi) >> 1;
        if (__ldg(batch + mid) < g + 1) lo = mid + 1; else hi = mid;
    }
    int end = lo;
    float acc = 0.f;
    int n = start;
    for (; n + 4 <= end; n += 4) {
        acc += __ldg(node + (size_t)(n + 0) * D + c);
        acc += __ldg(node + (size_t)(n + 1) * D + c);
        acc += __ldg(node + (size_t)(n + 2) * D + c);
        acc += __ldg(node + (size_t)(n + 3) * D + c);
    }
    for (; n < end; n++) acc += __ldg(node + (size_t)n * D + c);
    out[(size_t)g * D + c] = acc;
}

// ---------------- launch ----------------
extern "C" void kernel_launch(void* const* d_in, const int* in_sizes, int n_in,
                              void* d_out, int out_size) {
    const float* x = (const float*)d_in[0];
    const int* ei = (const int*)d_in[1];        // int32! (JAX x64 disabled)
    const int* batch = (const int*)d_in[2];     // int32!
    const float* fc_w = (const float*)d_in[3];
    const float* fc_b = (const float*)d_in[4];
    const float* Wl = (const float*)d_in[5];
    const float* bl = (const float*)d_in[6];
    const float* Wr = (const float*)d_in[7];
    const float* lng = (const float*)d_in[8];
    const float* lnb = (const float*)d_in[9];

    float* out_node = (float*)d_out;
    float* out_graph = out_node + (size_t)N_NODES * D;

    float *h, *agg, *inv;
    cudaGetSymbolAddress((void**)&h, g_h);
    cudaGetSymbolAddress((void**)&agg, g_agg);
    cudaGetSymbolAddress((void**)&inv, g_inv);

    // degrees (reused by all 3 layers)
    zero_kernel<<<(N_NODES / 4 + 255) / 256, 256>>>((float4*)inv, N_NODES / 4);
    count_deg_kernel<<<(N_EDGES + 255) / 256, 256>>>(ei, inv);
    finalize_inv_kernel<<<(N_NODES + 255) / 256, 256>>>(inv);

    const int GBLK = (N_NODES + 127) / 128;  // 313

    // input projection + ReLU
    gemm_fused<1, false, true><<<GBLK, 256>>>(
        x, fc_w, nullptr, nullptr, nullptr, fc_b, nullptr, nullptr, h, N_NODES);

    for (int i = 0; i < 3; i++) {
        zero_kernel<<<((N_NODES * D) / 4 + 255) / 256, 256>>>(
            (float4*)agg, (N_NODES * D) / 4);
        scatter_kernel<<<(N_EDGES * 32 + 255) / 256, 256>>>(ei, h, agg);
        if (i < 2) {
            gemm_fused<2, true, true><<<GBLK, 256>>>(
                agg, Wl + (size_t)i * D * D, h, Wr + (size_t)i * D * D, inv,
                bl + (size_t)i * D, lng + (size_t)i * D, lnb + (size_t)i * D,
                h, N_NODES);
        } else {
            gemm_fused<2, false, false><<<GBLK, 256>>>(
                agg, Wl + (size_t)i * D * D, h, Wr + (size_t)i * D * D, inv,
                bl + (size_t)i * D, nullptr, nullptr, out_node, N_NODES);
        }
    }

    graph_pool_kernel<<<N_GRAPHS, 128>>>(out_node, batch, out_graph);
}

// round 3
// speedup vs baseline: 1.2974x; 1.2974x over previous
#include <cuda_runtime.h>
#include <cstdint>

#define N_NODES 40000
#define N_EDGES 640000
#define N_GRAPHS 64
#define D 128
#define LN_EPS 1e-5f
#define SCAN_BLK 1024
#define N_SCAN_BLKS ((N_NODES + SCAN_BLK - 1) / SCAN_BLK)   // 40

// ---------------- scratch (no allocations allowed) ----------------
__device__ float g_h[(size_t)N_NODES * D];
__device__ float g_agg[(size_t)N_NODES * D];
__device__ int g_cnt[N_NODES];
__device__ int g_fill[N_NODES];
__device__ int g_scan[N_NODES];
__device__ int g_bsum[N_SCAN_BLKS];
__device__ int g_boff[N_SCAN_BLKS];
__device__ int g_rowptr[N_NODES + 1];
__device__ int g_col[N_EDGES];

// ---------------- f32x2 packed helpers (Blackwell FFMA2) ----------------
__device__ __forceinline__ unsigned long long pack2(float lo, float hi) {
    unsigned long long r;
    asm("mov.b64 %0, {%1, %2};" : "=l"(r) : "f"(lo), "f"(hi));
    return r;
}
__device__ __forceinline__ void fma2(unsigned long long& d, unsigned long long a,
                                     unsigned long long b) {
    asm("fma.rn.f32x2 %0, %1, %2, %0;" : "+l"(d) : "l"(a), "l"(b));
}

// ================= CSR build =================
__global__ void zero_cnt_kernel() {
    int i = blockIdx.x * blockDim.x + threadIdx.x;
    if (i < N_NODES) { g_cnt[i] = 0; g_fill[i] = 0; }
}

__global__ void count_kernel(const int* __restrict__ ei) {
    int e = blockIdx.x * blockDim.x + threadIdx.x;
    if (e < N_EDGES) atomicAdd(&g_cnt[__ldg(ei + N_EDGES + e)], 1);
}

__global__ __launch_bounds__(SCAN_BLK) void scan1_kernel() {
    __shared__ int sh[SCAN_BLK];
    int t = threadIdx.x;
    int i = blockIdx.x * SCAN_BLK + t;
    int v = (i < N_NODES) ? g_cnt[i] : 0;
    sh[t] = v;
    __syncthreads();
#pragma unroll
    for (int off = 1; off < SCAN_BLK; off <<= 1) {
        int x = (t >= off) ? sh[t - off] : 0;
        __syncthreads();
        sh[t] += x;
        __syncthreads();
    }
    if (i < N_NODES) g_scan[i] = sh[t];
    if (t == SCAN_BLK - 1) g_bsum[blockIdx.x] = sh[t];
}

__global__ void scan2_kernel() {
    if (threadIdx.x == 0) {
        int run = 0;
        for (int b = 0; b < N_SCAN_BLKS; b++) {
            g_boff[b] = run;
            run += g_bsum[b];
        }
    }
}

__global__ void scan3_kernel() {
    int i = blockIdx.x * blockDim.x + threadIdx.x;
    if (i < N_NODES) g_rowptr[i + 1] = g_scan[i] + g_boff[i >> 10];
    if (i == 0) g_rowptr[0] = 0;
}

__global__ void fill_kernel(const int* __restrict__ ei) {
    int e = blockIdx.x * blockDim.x + threadIdx.x;
    if (e < N_EDGES) {
        int s = __ldg(ei + e);
        int d = __ldg(ei + N_EDGES + e);
        int pos = g_rowptr[d] + atomicAdd(&g_fill[d], 1);
        g_col[pos] = s;
    }
}

// ================= gather: agg[n] = mean_{s in nbrs(n)} h[s] =================
__global__ __launch_bounds__(256) void gather_kernel(const float* __restrict__ h,
                                                     float* __restrict__ agg) {
    int warp = (blockIdx.x * 256 + threadIdx.x) >> 5;
    int lane = threadIdx.x & 31;
    if (warp >= N_NODES) return;
    int beg = __ldg(&g_rowptr[warp]);
    int end = __ldg(&g_rowptr[warp + 1]);
    float4 acc = make_float4(0.f, 0.f, 0.f, 0.f);
    int k = beg;
    for (; k + 2 <= end; k += 2) {
        int s0 = __ldg(&g_col[k]);
        int s1 = __ldg(&g_col[k + 1]);
        float4 v0 = __ldg((const float4*)(h + (size_t)s0 * D) + lane);
        float4 v1 = __ldg((const float4*)(h + (size_t)s1 * D) + lane);
        acc.x += v0.x + v1.x; acc.y += v0.y + v1.y;
        acc.z += v0.z + v1.z; acc.w += v0.w + v1.w;
    }
    if (k < end) {
        int s0 = __ldg(&g_col[k]);
        float4 v0 = __ldg((const float4*)(h + (size_t)s0 * D) + lane);
        acc.x += v0.x; acc.y += v0.y; acc.z += v0.z; acc.w += v0.w;
    }
    float sc = 1.0f / (float)max(end - beg, 1);
    acc.x *= sc; acc.y *= sc; acc.z *= sc; acc.w *= sc;
    ((float4*)(agg + (size_t)warp * D))[lane] = acc;
}

// ================= fused GEMM (pipelined, double-buffered) =================
// out = A0 @ W0^T (+ A1 @ W1^T) + bias, optional LayerNorm + ReLU.
// NCHUNK=8 -> single segment (A0,W0); NCHUNK=16 -> two segments.
template <int NCHUNK, bool DO_LN, bool DO_RELU>
__global__ __launch_bounds__(256, 2) void gemm_fused(
    const float* __restrict__ A0, const float* __restrict__ W0,
    const float* __restrict__ A1, const float* __restrict__ W1,
    const float* __restrict__ bias,
    const float* __restrict__ lng, const float* __restrict__ lnb,
    float* __restrict__ out, int nrows) {
    // [buf][A=0/B=1][k][r]
    __shared__ __align__(16) float sbuf[2][2][16][132];

    const int tid = threadIdx.x;
    const int tx = tid & 15;
    const int ty = tid >> 4;
    const int row0 = blockIdx.x * 128;

    union Acc {
        unsigned long long u[8][4];
        float f[8][8];
    } acc;
#pragma unroll
    for (int i = 0; i < 8; i++)
#pragma unroll
        for (int j = 0; j < 4; j++) acc.u[i][j] = 0ULL;

    // thread's staging slots: slot = tid + it*256; r = slot>>2; kq = slot&3
    const int r_s[2] = {tid >> 2, (tid + 256) >> 2};
    const int kq_s[2] = {tid & 3, (tid + 256) & 3};

    auto seg_of = [&](int c, const float*& A, const float*& W, int& kb) {
        if (NCHUNK == 8 || c < 8) {
            A = A0; W = W0; kb = c * 16;
        } else {
            A = A1; W = W1; kb = (c - 8) * 16;
        }
    };

    float4 pa[2], pw[2];

    // preload chunk 0 directly into buffer 0
    {
        const float* A; const float* W; int kb;
        seg_of(0, A, W, kb);
#pragma unroll
        for (int it = 0; it < 2; it++) {
            int r = r_s[it], kq = kq_s[it];
            int grow = row0 + r;
            float4 v = make_float4(0.f, 0.f, 0.f, 0.f);
            if (grow < nrows)
                v = __ldg((const float4*)(A + (size_t)grow * D + kb) + kq);
            float4 w = __ldg((const float4*)(W + (size_t)r * D + kb) + kq);
            sbuf[0][0][kq * 4 + 0][r] = v.x;
            sbuf[0][0][kq * 4 + 1][r] = v.y;
            sbuf[0][0][kq * 4 + 2][r] = v.z;
            sbuf[0][0][kq * 4 + 3][r] = v.w;
            sbuf[0][1][kq * 4 + 0][r] = w.x;
            sbuf[0][1][kq * 4 + 1][r] = w.y;
            sbuf[0][1][kq * 4 + 2][r] = w.z;
            sbuf[0][1][kq * 4 + 3][r] = w.w;
        }
    }
    __syncthreads();

#pragma unroll 1
    for (int c = 0; c < NCHUNK; c++) {
        const int cur = c & 1;
        // prefetch next chunk to registers
        if (c + 1 < NCHUNK) {
            const float* A; const float* W; int kb;
            seg_of(c + 1, A, W, kb);
#pragma unroll
            for (int it = 0; it < 2; it++) {
                int r = r_s[it], kq = kq_s[it];
                int grow = row0 + r;
                pa[it] = make_float4(0.f, 0.f, 0.f, 0.f);
                if (grow < nrows)
                    pa[it] = __ldg((const float4*)(A + (size_t)grow * D + kb) + kq);
                pw[it] = __ldg((const float4*)(W + (size_t)r * D + kb) + kq);
            }
        }
        // compute from current buffer
#pragma unroll
        for (int k = 0; k < 16; k++) {
            const unsigned long long* pb =
                (const unsigned long long*)&sbuf[cur][1][k][tx * 8];
            unsigned long long b0 = pb[0], b1 = pb[1], b2 = pb[2], b3 = pb[3];
#pragma unroll
            for (int i = 0; i < 8; i++) {
                float a = sbuf[cur][0][k][ty * 8 + i];
                unsigned long long a2 = pack2(a, a);
                fma2(acc.u[i][0], a2, b0);
                fma2(acc.u[i][1], a2, b1);
                fma2(acc.u[i][2], a2, b2);
                fma2(acc.u[i][3], a2, b3);
            }
        }
        // store prefetched chunk into the other buffer
        if (c + 1 < NCHUNK) {
            const int nxt = cur ^ 1;
#pragma unroll
            for (int it = 0; it < 2; it++) {
                int r = r_s[it], kq = kq_s[it];
                sbuf[nxt][0][kq * 4 + 0][r] = pa[it].x;
                sbuf[nxt][0][kq * 4 + 1][r] = pa[it].y;
                sbuf[nxt][0][kq * 4 + 2][r] = pa[it].z;
                sbuf[nxt][0][kq * 4 + 3][r] = pa[it].w;
                sbuf[nxt][1][kq * 4 + 0][r] = pw[it].x;
                sbuf[nxt][1][kq * 4 + 1][r] = pw[it].y;
                sbuf[nxt][1][kq * 4 + 2][r] = pw[it].z;
                sbuf[nxt][1][kq * 4 + 3][r] = pw[it].w;
            }
            __syncthreads();
        }
    }

    // ---------------- epilogue ----------------
    float bcol[8];
#pragma unroll
    for (int j = 0; j < 8; j++) bcol[j] = __ldg(bias + tx * 8 + j);
#pragma unroll
    for (int i = 0; i < 8; i++)
#pragma unroll
        for (int j = 0; j < 8; j++) acc.f[i][j] += bcol[j];

    if (DO_LN) {
        __syncthreads();  // compute done, safe to alias sbuf
        float* red0 = &sbuf[0][0][0][0];          // 128*17
        float* red1 = red0 + 128 * 17;            // 128*17
        float* s_mu = red1 + 128 * 17;            // 128
        float* s_rs = s_mu + 128;                 // 128
#pragma unroll
        for (int i = 0; i < 8; i++) {
            float s = 0.f, q = 0.f;
#pragma unroll
            for (int j = 0; j < 8; j++) {
                s += acc.f[i][j];
                q += acc.f[i][j] * acc.f[i][j];
            }
            red0[(ty * 8 + i) * 17 + tx] = s;
            red1[(ty * 8 + i) * 17 + tx] = q;
        }
        __syncthreads();
        if (tid < 128) {
            float s = 0.f, q = 0.f;
#pragma unroll
            for (int t = 0; t < 16; t++) {
                s += red0[tid * 17 + t];
                q += red1[tid * 17 + t];
            }
            float mu = s * (1.0f / 128.0f);
            float var = q * (1.0f / 128.0f) - mu * mu;
            s_mu[tid] = mu;
            s_rs[tid] = rsqrtf(var + LN_EPS);
        }
        __syncthreads();
        float gj[8], bj[8];
#pragma unroll
        for (int j = 0; j < 8; j++) {
            gj[j] = __ldg(lng + tx * 8 + j);
            bj[j] = __ldg(lnb + tx * 8 + j);
        }
#pragma unroll
        for (int i = 0; i < 8; i++) {
            float mu = s_mu[ty * 8 + i];
            float rs = s_rs[ty * 8 + i];
#pragma unroll
            for (int j = 0; j < 8; j++)
                acc.f[i][j] = (acc.f[i][j] - mu) * rs * gj[j] + bj[j];
        }
    }

    if (DO_RELU) {
#pragma unroll
        for (int i = 0; i < 8; i++)
#pragma unroll
            for (int j = 0; j < 8; j++) acc.f[i][j] = fmaxf(acc.f[i][j], 0.f);
    }

#pragma unroll
    for (int i = 0; i < 8; i++) {
        int grow = row0 + ty * 8 + i;
        if (grow < nrows) {
            float4* po = (float4*)(out + (size_t)grow * D + tx * 8);
            po[0] = make_float4(acc.f[i][0], acc.f[i][1], acc.f[i][2], acc.f[i][3]);
            po[1] = make_float4(acc.f[i][4], acc.f[i][5], acc.f[i][6], acc.f[i][7]);
        }
    }
}

// ---------------- per-graph sum pool (batch sorted -> no atomics) ----------------
__global__ void graph_pool_kernel(const float* __restrict__ node,
                                  const int* __restrict__ batch,
                                  float* __restrict__ out) {
    int g = blockIdx.x;
    int c = threadIdx.x;  // 0..127
    int lo = 0, hi = N_NODES;
    while (lo < hi) {
        int mid = (lo + hi) >> 1;
        if (__ldg(batch + mid) < g) lo = mid + 1; else hi = mid;
    }
    int start = lo;
    hi = N_NODES;
    while (lo < hi) {
        int mid = (lo + hi) >> 1;
        if (__ldg(batch + mid) < g + 1) lo = mid + 1; else hi = mid;
    }
    int end = lo;
    float acc = 0.f;
    int n = start;
    for (; n + 4 <= end; n += 4) {
        acc += __ldg(node + (size_t)(n + 0) * D + c);
        acc += __ldg(node + (size_t)(n + 1) * D + c);
        acc += __ldg(node + (size_t)(n + 2) * D + c);
        acc += __ldg(node + (size_t)(n + 3) * D + c);
    }
    for (; n < end; n++) acc += __ldg(node + (size_t)n * D + c);
    out[(size_t)g * D + c] = acc;
}

// ---------------- launch ----------------
extern "C" void kernel_launch(void* const* d_in, const int* in_sizes, int n_in,
                              void* d_out, int out_size) {
    const float* x = (const float*)d_in[0];
    const int* ei = (const int*)d_in[1];
    const int* batch = (const int*)d_in[2];
    const float* fc_w = (const float*)d_in[3];
    const float* fc_b = (const float*)d_in[4];
    const float* Wl = (const float*)d_in[5];
    const float* bl = (const float*)d_in[6];
    const float* Wr = (const float*)d_in[7];
    const float* lng = (const float*)d_in[8];
    const float* lnb = (const float*)d_in[9];

    float* out_node = (float*)d_out;
    float* out_graph = out_node + (size_t)N_NODES * D;

    float *h, *agg;
    cudaGetSymbolAddress((void**)&h, g_h);
    cudaGetSymbolAddress((void**)&agg, g_agg);

    // CSR build
    zero_cnt_kernel<<<(N_NODES + 255) / 256, 256>>>();
    count_kernel<<<(N_EDGES + 255) / 256, 256>>>(ei);
    scan1_kernel<<<N_SCAN_BLKS, SCAN_BLK>>>();
    scan2_kernel<<<1, 32>>>();
    scan3_kernel<<<(N_NODES + 255) / 256, 256>>>();
    fill_kernel<<<(N_EDGES + 255) / 256, 256>>>(ei);

    const int GBLK = (N_NODES + 127) / 128;  // 313

    // input projection + ReLU
    gemm_fused<8, false, true><<<GBLK, 256>>>(
        x, fc_w, nullptr, nullptr, fc_b, nullptr, nullptr, h, N_NODES);

    for (int i = 0; i < 3; i++) {
        gather_kernel<<<(N_NODES * 32 + 255) / 256, 256>>>(h, agg);
        if (i < 2) {
            gemm_fused<16, true, true><<<GBLK, 256>>>(
                agg, Wl + (size_t)i * D * D, h, Wr + (size_t)i * D * D,
                bl + (size_t)i * D, lng + (size_t)i * D, lnb + (size_t)i * D,
                h, N_NODES);
        } else {
            gemm_fused<16, false, false><<<GBLK, 256>>>(
                agg, Wl + (size_t)i * D * D, h, Wr + (size_t)i * D * D,
                bl + (size_t)i * D, nullptr, nullptr, out_node, N_NODES);
        }
    }

    graph_pool_kernel<<<N_GRAPHS, 128>>>(out_node, batch, out_graph);
}

// round 5
// speedup vs baseline: 1.9219x; 1.4813x over previous
#include <cuda_runtime.h>
#include <cuda_bf16.h>
#include <cstdint>

#define N_NODES 40000
#define N_EDGES 640000
#define N_GRAPHS 64
#define D 128
#define LN_EPS 1e-5f
#define SCAN_BLK 1024
#define N_SCAN_BLKS ((N_NODES + SCAN_BLK - 1) / SCAN_BLK)   // 40

// ---------------- scratch (no allocations allowed) ----------------
__device__ float g_h[(size_t)N_NODES * D];
__device__ float g_agg[(size_t)N_NODES * D];
__device__ int g_cnt[N_NODES];
__device__ int g_fill[N_NODES];
__device__ int g_scan[N_NODES];
__device__ int g_bsum[N_SCAN_BLKS];
__device__ int g_boff[N_SCAN_BLKS];
__device__ int g_rowptr[N_NODES + 1];
__device__ int g_col[N_EDGES];

// ================= helpers =================
__device__ __forceinline__ uint32_t smem_u32(const void* p) {
    uint32_t a;
    asm("{ .reg .u64 t; cvta.to.shared.u64 t, %1; cvt.u32.u64 %0, t; }"
        : "=r"(a) : "l"(p));
    return a;
}
// pack (lo, hi) floats -> bf16x2 (lo in low half)
__device__ __forceinline__ uint32_t cvt_bf16x2(float lo, float hi) {
    uint32_t r;
    asm("cvt.rn.bf16x2.f32 %0, %1, %2;" : "=r"(r) : "f"(hi), "f"(lo));
    return r;
}
__device__ __forceinline__ void ldmx4(uint32_t* r, uint32_t addr) {
    asm volatile("ldmatrix.sync.aligned.m8n8.x4.shared.b16 {%0,%1,%2,%3}, [%4];"
                 : "=r"(r[0]), "=r"(r[1]), "=r"(r[2]), "=r"(r[3]) : "r"(addr));
}
__device__ __forceinline__ void mma_bf16(float* d, const uint32_t* a,
                                         const uint32_t* b) {
    asm volatile(
        "mma.sync.aligned.m16n8k16.row.col.f32.bf16.bf16.f32 "
        "{%0,%1,%2,%3}, {%4,%5,%6,%7}, {%8,%9}, {%0,%1,%2,%3};"
        : "+f"(d[0]), "+f"(d[1]), "+f"(d[2]), "+f"(d[3])
        : "r"(a[0]), "r"(a[1]), "r"(a[2]), "r"(a[3]), "r"(b[0]), "r"(b[1]));
}

// ================= CSR build =================
__global__ void zero_cnt_kernel() {
    int i = blockIdx.x * blockDim.x + threadIdx.x;
    if (i < N_NODES) { g_cnt[i] = 0; g_fill[i] = 0; }
}
__global__ void count_kernel(const int* __restrict__ ei) {
    int e = blockIdx.x * blockDim.x + threadIdx.x;
    if (e < N_EDGES) atomicAdd(&g_cnt[__ldg(ei + N_EDGES + e)], 1);
}
__global__ __launch_bounds__(SCAN_BLK) void scan1_kernel() {
    __shared__ int sh[SCAN_BLK];
    int t = threadIdx.x;
    int i = blockIdx.x * SCAN_BLK + t;
    int v = (i < N_NODES) ? g_cnt[i] : 0;
    sh[t] = v;
    __syncthreads();
#pragma unroll
    for (int off = 1; off < SCAN_BLK; off <<= 1) {
        int x = (t >= off) ? sh[t - off] : 0;
        __syncthreads();
        sh[t] += x;
        __syncthreads();
    }
    if (i < N_NODES) g_scan[i] = sh[t];
    if (t == SCAN_BLK - 1) g_bsum[blockIdx.x] = sh[t];
}
__global__ void scan2_kernel() {
    if (threadIdx.x == 0) {
        int run = 0;
        for (int b = 0; b < N_SCAN_BLKS; b++) { g_boff[b] = run; run += g_bsum[b]; }
    }
}
__global__ void scan3_kernel() {
    int i = blockIdx.x * blockDim.x + threadIdx.x;
    if (i < N_NODES) g_rowptr[i + 1] = g_scan[i] + g_boff[i >> 10];
    if (i == 0) g_rowptr[0] = 0;
}
__global__ void fill_kernel(const int* __restrict__ ei) {
    int e = blockIdx.x * blockDim.x + threadIdx.x;
    if (e < N_EDGES) {
        int s = __ldg(ei + e);
        int d = __ldg(ei + N_EDGES + e);
        int pos = g_rowptr[d] + atomicAdd(&g_fill[d], 1);
        g_col[pos] = s;
    }
}

// ================= gather: agg[n] = mean_{s in nbrs(n)} h[s] =================
__global__ __launch_bounds__(256) void gather_kernel(const float* __restrict__ h,
                                                     float* __restrict__ agg) {
    int warp = (blockIdx.x * 256 + threadIdx.x) >> 5;
    int lane = threadIdx.x & 31;
    if (warp >= N_NODES) return;
    int beg = __ldg(&g_rowptr[warp]);
    int end = __ldg(&g_rowptr[warp + 1]);
    float4 acc = make_float4(0.f, 0.f, 0.f, 0.f);
    int k = beg;
    for (; k + 2 <= end; k += 2) {
        int s0 = __ldg(&g_col[k]);
        int s1 = __ldg(&g_col[k + 1]);
        float4 v0 = __ldg((const float4*)(h + (size_t)s0 * D) + lane);
        float4 v1 = __ldg((const float4*)(h + (size_t)s1 * D) + lane);
        acc.x += v0.x + v1.x; acc.y += v0.y + v1.y;
        acc.z += v0.z + v1.z; acc.w += v0.w + v1.w;
    }
    if (k < end) {
        int s0 = __ldg(&g_col[k]);
        float4 v0 = __ldg((const float4*)(h + (size_t)s0 * D) + lane);
        acc.x += v0.x; acc.y += v0.y; acc.z += v0.z; acc.w += v0.w;
    }
    float sc = 1.0f / (float)max(end - beg, 1);
    acc.x *= sc; acc.y *= sc; acc.z *= sc; acc.w *= sc;
    ((float4*)(agg + (size_t)warp * D))[lane] = acc;
}

// ================= mma.sync split-bf16 GEMM =================
// D[128x128] = sum_seg A_seg @ W_seg^T via 3 HMMA passes (hi*hi, hi*lo, lo*hi),
// + bias, optional LayerNorm + ReLU. 8 warps (4x2), each 32x64 output.
#define TSTRIDE 136                       // bf16 elems per smem row (padded)
#define TROWB (TSTRIDE * 2)               // 272 bytes
#define TILE_B (128 * TROWB)              // 34816 bytes per tile
#define OFF_AHI 0
#define OFF_ALO (OFF_AHI + TILE_B)
#define OFF_WHI (OFF_ALO + TILE_B)
#define OFF_WLO (OFF_WHI + TILE_B)
#define GEMM_SMEM (4 * TILE_B)            // 139264

template <int NSEG, bool DO_LN, bool DO_RELU>
__global__ __launch_bounds__(256, 1) void gemm_mma(
    const float* __restrict__ A0, const float* __restrict__ W0,
    const float* __restrict__ A1, const float* __restrict__ W1,
    const float* __restrict__ bias,
    const float* __restrict__ lng, const float* __restrict__ lnb,
    float* __restrict__ out, int nrows) {
    extern __shared__ __align__(16) char smem[];
    const uint32_t sb = smem_u32(smem);
    const int tid = threadIdx.x;
    const int lane = tid & 31;
    const int wid = tid >> 5;
    const int warpM = wid >> 1;           // 0..3 -> rows warpM*32
    const int warpN = wid & 1;            // 0..1 -> cols warpN*64
    const int row0 = blockIdx.x * 128;
    const int g = lane >> 2;              // group 0..7
    const int t = lane & 3;

    float d[2][8][4];
#pragma unroll
    for (int mt = 0; mt < 2; mt++)
#pragma unroll
        for (int nt = 0; nt < 8; nt++)
#pragma unroll
            for (int e = 0; e < 4; e++) d[mt][nt][e] = 0.f;

    // per-lane ldmatrix base offsets
    const int frag = lane >> 3;
    const uint32_t a_rel = (uint32_t)((warpM * 32 + (frag & 1) * 8 + (lane & 7)) * TROWB +
                                      (frag >> 1) * 16);
    const uint32_t b_rel = (uint32_t)((warpN * 64 + (frag >> 1) * 8 + (lane & 7)) * TROWB +
                                      (frag & 1) * 16);

#pragma unroll
    for (int seg = 0; seg < NSEG; seg++) {
        const float* A = (seg == 0) ? A0 : A1;
        const float* W = (seg == 0) ? W0 : W1;
        if (seg > 0) __syncthreads();  // previous reads done before refill

        // -------- fill: fp32 -> bf16 hi/lo tiles --------
#pragma unroll 4
        for (int it = 0; it < 16; it++) {
            int r = wid + it * 8;        // 0..127
            int col = lane * 4;          // 0..124
            uint32_t off = (uint32_t)(r * TROWB + col * 2);

            float4 v = make_float4(0.f, 0.f, 0.f, 0.f);
            int grow = row0 + r;
            if (grow < nrows) v = __ldg((const float4*)(A + (size_t)grow * D) + lane);
            float hx = __bfloat162float(__float2bfloat16_rn(v.x));
            float hy = __bfloat162float(__float2bfloat16_rn(v.y));
            float hz = __bfloat162float(__float2bfloat16_rn(v.z));
            float hw = __bfloat162float(__float2bfloat16_rn(v.w));
            *(uint2*)(smem + OFF_AHI + off) =
                make_uint2(cvt_bf16x2(hx, hy), cvt_bf16x2(hz, hw));
            *(uint2*)(smem + OFF_ALO + off) =
                make_uint2(cvt_bf16x2(v.x - hx, v.y - hy),
                           cvt_bf16x2(v.z - hz, v.w - hw));

            float4 w = __ldg((const float4*)(W + (size_t)r * D) + lane);
            float gx = __bfloat162float(__float2bfloat16_rn(w.x));
            float gy = __bfloat162float(__float2bfloat16_rn(w.y));
            float gz = __bfloat162float(__float2bfloat16_rn(w.z));
            float gw = __bfloat162float(__float2bfloat16_rn(w.w));
            *(uint2*)(smem + OFF_WHI + off) =
                make_uint2(cvt_bf16x2(gx, gy), cvt_bf16x2(gz, gw));
            *(uint2*)(smem + OFF_WLO + off) =
                make_uint2(cvt_bf16x2(w.x - gx, w.y - gy),
                           cvt_bf16x2(w.z - gz, w.w - gw));
        }
        __syncthreads();

        // -------- 3 passes: (Ahi,Whi), (Ahi,Wlo), (Alo,Whi) --------
#pragma unroll
        for (int pass = 0; pass < 3; pass++) {
            const uint32_t abase = sb + ((pass == 2) ? OFF_ALO : OFF_AHI) + a_rel;
            const uint32_t wbase = sb + ((pass == 1) ? OFF_WLO : OFF_WHI) + b_rel;
#pragma unroll
            for (int ks = 0; ks < 8; ks++) {
                uint32_t af[2][4];
#pragma unroll
                for (int mt = 0; mt < 2; mt++)
                    ldmx4(af[mt], abase + mt * (16 * TROWB) + ks * 32);
                uint32_t bf[8][2];
#pragma unroll
                for (int ntp = 0; ntp < 4; ntp++) {
                    uint32_t r4[4];
                    ldmx4(r4, wbase + ntp * (16 * TROWB) + ks * 32);
                    bf[2 * ntp][0] = r4[0]; bf[2 * ntp][1] = r4[1];
                    bf[2 * ntp + 1][0] = r4[2]; bf[2 * ntp + 1][1] = r4[3];
                }
#pragma unroll
                for (int mt = 0; mt < 2; mt++)
#pragma unroll
                    for (int nt = 0; nt < 8; nt++)
                        mma_bf16(d[mt][nt], af[mt], bf[nt]);
            }
        }
    }

    // ================= epilogue =================
    // d[mt][nt][e]: e0:(row G, col C) e1:(G, C+1) e2:(G+8, C) e3:(G+8, C+1)
    // G = warpM*32 + mt*16 + g ; C = warpN*64 + nt*8 + 2t
    // bias
#pragma unroll
    for (int nt = 0; nt < 8; nt++) {
        int C = warpN * 64 + nt * 8 + 2 * t;
        float2 bv = __ldg((const float2*)(bias + C));
#pragma unroll
        for (int mt = 0; mt < 2; mt++) {
            d[mt][nt][0] += bv.x; d[mt][nt][1] += bv.y;
            d[mt][nt][2] += bv.x; d[mt][nt][3] += bv.y;
        }
    }

    if (DO_LN) {
        __syncthreads();  // all ldmatrix reads done; reuse smem
        float* red_s = (float*)smem;        // [128][2]
        float* red_q = red_s + 256;         // [128][2]
        float* s_mu = red_q + 256;          // [128]
        float* s_rs = s_mu + 128;           // [128]
#pragma unroll
        for (int mt = 0; mt < 2; mt++) {
#pragma unroll
            for (int rh = 0; rh < 2; rh++) {
                float s = 0.f, q = 0.f;
#pragma unroll
                for (int nt = 0; nt < 8; nt++) {
                    float v0 = d[mt][nt][2 * rh], v1 = d[mt][nt][2 * rh + 1];
                    s += v0 + v1;
                    q += v0 * v0 + v1 * v1;
                }
                s += __shfl_xor_sync(0xffffffff, s, 1);
                s += __shfl_xor_sync(0xffffffff, s, 2);
                q += __shfl_xor_sync(0xffffffff, q, 1);
                q += __shfl_xor_sync(0xffffffff, q, 2);
                if (t == 0) {
                    int r = warpM * 32 + mt * 16 + rh * 8 + g;
                    red_s[r * 2 + warpN] = s;
                    red_q[r * 2 + warpN] = q;
                }
            }
        }
        __syncthreads();
        if (tid < 128) {
            float st = red_s[tid * 2] + red_s[tid * 2 + 1];
            float qt = red_q[tid * 2] + red_q[tid * 2 + 1];
            float mu = st * (1.0f / 128.0f);
            float var = qt * (1.0f / 128.0f) - mu * mu;
            s_mu[tid] = mu;
            s_rs[tid] = rsqrtf(var + LN_EPS);
        }
        __syncthreads();
#pragma unroll
        for (int nt = 0; nt < 8; nt++) {
            int C = warpN * 64 + nt * 8 + 2 * t;
            float2 gv = __ldg((const float2*)(lng + C));
            float2 bv = __ldg((const float2*)(lnb + C));
#pragma unroll
            for (int mt = 0; mt < 2; mt++) {
#pragma unroll
                for (int rh = 0; rh < 2; rh++) {
                    int r = warpM * 32 + mt * 16 + rh * 8 + g;
                    float mu = s_mu[r], rs = s_rs[r];
                    d[mt][nt][2 * rh] = (d[mt][nt][2 * rh] - mu) * rs * gv.x + bv.x;
                    d[mt][nt][2 * rh + 1] =
                        (d[mt][nt][2 * rh + 1] - mu) * rs * gv.y + bv.y;
                }
            }
        }
    }

    if (DO_RELU) {
#pragma unroll
        for (int mt = 0; mt < 2; mt++)
#pragma unroll
            for (int nt = 0; nt < 8; nt++)
#pragma unroll
                for (int e = 0; e < 4; e++) d[mt][nt][e] = fmaxf(d[mt][nt][e], 0.f);
    }

    // store
#pragma unroll
    for (int mt = 0; mt < 2; mt++) {
#pragma unroll
        for (int rh = 0; rh < 2; rh++) {
            int R = row0 + warpM * 32 + mt * 16 + rh * 8 + g;
            if (R < nrows) {
                float* pr = out + (size_t)R * D + warpN * 64 + 2 * t;
#pragma unroll
                for (int nt = 0; nt < 8; nt++)
                    *(float2*)(pr + nt * 8) =
                        make_float2(d[mt][nt][2 * rh], d[mt][nt][2 * rh + 1]);
            }
        }
    }
}

// ---------------- per-graph sum pool (batch sorted -> no atomics) ----------------
__global__ void graph_pool_kernel(const float* __restrict__ node,
                                  const int* __restrict__ batch,
                                  float* __restrict__ out) {
    int g = blockIdx.x;
    int c = threadIdx.x;  // 0..127
    int lo = 0, hi = N_NODES;
    while (lo < hi) {
        int mid = (lo + hi) >> 1;
        if (__ldg(batch + mid) < g) lo = mid + 1; else hi = mid;
    }
    int start = lo;
    hi = N_NODES;
    while (lo < hi) {
        int mid = (lo + hi) >> 1;
        if (__ldg(batch + mid) < g + 1) lo = mid + 1; else hi = mid;
    }
    int end = lo;
    float acc = 0.f;
    int n = start;
    for (; n + 4 <= end; n += 4) {
        acc += __ldg(node + (size_t)(n + 0) * D + c);
        acc += __ldg(node + (size_t)(n + 1) * D + c);
        acc += __ldg(node + (size_t)(n + 2) * D + c);
        acc += __ldg(node + (size_t)(n + 3) * D + c);
    }
    for (; n < end; n++) acc += __ldg(node + (size_t)n * D + c);
    out[(size_t)g * D + c] = acc;
}

// ---------------- launch ----------------
extern "C" void kernel_launch(void* const* d_in, const int* in_sizes, int n_in,
                              void* d_out, int out_size) {
    const float* x = (const float*)d_in[0];
    const int* ei = (const int*)d_in[1];
    const int* batch = (const int*)d_in[2];
    const float* fc_w = (const float*)d_in[3];
    const float* fc_b = (const float*)d_in[4];
    const float* Wl = (const float*)d_in[5];
    const float* bl = (const float*)d_in[6];
    const float* Wr = (const float*)d_in[7];
    const float* lng = (const float*)d_in[8];
    const float* lnb = (const float*)d_in[9];

    float* out_node = (float*)d_out;
    float* out_graph = out_node + (size_t)N_NODES * D;

    float *h, *agg;
    cudaGetSymbolAddress((void**)&h, g_h);
    cudaGetSymbolAddress((void**)&agg, g_agg);

    cudaFuncSetAttribute(gemm_mma<1, false, true>,
                         cudaFuncAttributeMaxDynamicSharedMemorySize, GEMM_SMEM);
    cudaFuncSetAttribute(gemm_mma<2, true, true>,
                         cudaFuncAttributeMaxDynamicSharedMemorySize, GEMM_SMEM);
    cudaFuncSetAttribute(gemm_mma<2, false, false>,
                         cudaFuncAttributeMaxDynamicSharedMemorySize, GEMM_SMEM);

    // CSR build
    zero_cnt_kernel<<<(N_NODES + 255) / 256, 256>>>();
    count_kernel<<<(N_EDGES + 255) / 256, 256>>>(ei);
    scan1_kernel<<<N_SCAN_BLKS, SCAN_BLK>>>();
    scan2_kernel<<<1, 32>>>();
    scan3_kernel<<<(N_NODES + 255) / 256, 256>>>();
    fill_kernel<<<(N_EDGES + 255) / 256, 256>>>(ei);

    const int GBLK = (N_NODES + 127) / 128;  // 313

    // input projection + ReLU
    gemm_mma<1, false, true><<<GBLK, 256, GEMM_SMEM>>>(
        x, fc_w, nullptr, nullptr, fc_b, nullptr, nullptr, h, N_NODES);

    for (int i = 0; i < 3; i++) {
        gather_kernel<<<(N_NODES * 32 + 255) / 256, 256>>>(h, agg);
        if (i < 2) {
            gemm_mma<2, true, true><<<GBLK, 256, GEMM_SMEM>>>(
                agg, Wl + (size_t)i * D * D, h, Wr + (size_t)i * D * D,
                bl + (size_t)i * D, lng + (size_t)i * D, lnb + (size_t)i * D,
                h, N_NODES);
        } else {
            gemm_mma<2, false, false><<<GBLK, 256, GEMM_SMEM>>>(
                agg, Wl + (size_t)i * D * D, h, Wr + (size_t)i * D * D,
                bl + (size_t)i * D, nullptr, nullptr, out_node, N_NODES);
        }
    }

    graph_pool_kernel<<<N_GRAPHS, 128>>>(out_node, batch, out_graph);
}

// round 6
// speedup vs baseline: 2.6615x; 1.3848x over previous
#include <cuda_runtime.h>
#include <cuda_fp16.h>
#include <cstdint>

#define N_NODES 40000
#define N_EDGES 640000
#define N_GRAPHS 64
#define D 128
#define LN_EPS 1e-5f
#define SCAN_BLK 1024
#define N_SCAN_BLKS ((N_NODES + SCAN_BLK - 1) / SCAN_BLK)   // 40

// ---------------- scratch (no allocations allowed) ----------------
__device__ __half g_h[(size_t)N_NODES * D];
__device__ __half g_agg[(size_t)N_NODES * D];
__device__ int g_cnt[N_NODES];
__device__ int g_fill[N_NODES];
__device__ int g_scan[N_NODES];
__device__ int g_bsum[N_SCAN_BLKS];
__device__ int g_boff[N_SCAN_BLKS];
__device__ int g_rowptr[N_NODES + 1];
__device__ int g_col[N_EDGES];

// ================= helpers =================
__device__ __forceinline__ uint32_t smem_u32(const void* p) {
    uint32_t a;
    asm("{ .reg .u64 t; cvta.to.shared.u64 t, %1; cvt.u32.u64 %0, t; }"
        : "=r"(a) : "l"(p));
    return a;
}
// pack (lo, hi) floats -> f16x2 (lo in low half)
__device__ __forceinline__ uint32_t cvt_f16x2(float lo, float hi) {
    uint32_t r;
    asm("cvt.rn.f16x2.f32 %0, %1, %2;" : "=r"(r) : "f"(hi), "f"(lo));
    return r;
}
__device__ __forceinline__ void ldmx4(uint32_t* r, uint32_t addr) {
    asm volatile("ldmatrix.sync.aligned.m8n8.x4.shared.b16 {%0,%1,%2,%3}, [%4];"
                 : "=r"(r[0]), "=r"(r[1]), "=r"(r[2]), "=r"(r[3]) : "r"(addr));
}
__device__ __forceinline__ void mma_fp16(float* d, const uint32_t* a,
                                         const uint32_t* b) {
    asm volatile(
        "mma.sync.aligned.m16n8k16.row.col.f32.f16.f16.f32 "
        "{%0,%1,%2,%3}, {%4,%5,%6,%7}, {%8,%9}, {%0,%1,%2,%3};"
        : "+f"(d[0]), "+f"(d[1]), "+f"(d[2]), "+f"(d[3])
        : "r"(a[0]), "r"(a[1]), "r"(a[2]), "r"(a[3]), "r"(b[0]), "r"(b[1]));
}

// ================= CSR build =================
__global__ void zero_cnt_kernel() {
    int i = blockIdx.x * blockDim.x + threadIdx.x;
    if (i < N_NODES) { g_cnt[i] = 0; g_fill[i] = 0; }
}
__global__ void count_kernel(const int* __restrict__ ei) {
    int e = blockIdx.x * blockDim.x + threadIdx.x;
    if (e < N_EDGES) atomicAdd(&g_cnt[__ldg(ei + N_EDGES + e)], 1);
}
__global__ __launch_bounds__(SCAN_BLK) void scan1_kernel() {
    __shared__ int sh[SCAN_BLK];
    int t = threadIdx.x;
    int i = blockIdx.x * SCAN_BLK + t;
    int v = (i < N_NODES) ? g_cnt[i] : 0;
    sh[t] = v;
    __syncthreads();
#pragma unroll
    for (int off = 1; off < SCAN_BLK; off <<= 1) {
        int x = (t >= off) ? sh[t - off] : 0;
        __syncthreads();
        sh[t] += x;
        __syncthreads();
    }
    if (i < N_NODES) g_scan[i] = sh[t];
    if (t == SCAN_BLK - 1) g_bsum[blockIdx.x] = sh[t];
}
__global__ void scan2_kernel() {
    __shared__ int sh[64];
    int t = threadIdx.x;
    int v = (t < N_SCAN_BLKS) ? g_bsum[t] : 0;
    sh[t] = v;
    __syncthreads();
#pragma unroll
    for (int off = 1; off < 64; off <<= 1) {
        int x = (t >= off) ? sh[t - off] : 0;
        __syncthreads();
        sh[t] += x;
        __syncthreads();
    }
    if (t < N_SCAN_BLKS) g_boff[t] = sh[t] - v;  // exclusive
}
__global__ void scan3_kernel() {
    int i = blockIdx.x * blockDim.x + threadIdx.x;
    if (i < N_NODES) g_rowptr[i + 1] = g_scan[i] + g_boff[i >> 10];
    if (i == 0) g_rowptr[0] = 0;
}
__global__ void fill_kernel(const int* __restrict__ ei) {
    int e = blockIdx.x * blockDim.x + threadIdx.x;
    if (e < N_EDGES) {
        int s = __ldg(ei + e);
        int d = __ldg(ei + N_EDGES + e);
        int pos = g_rowptr[d] + atomicAdd(&g_fill[d], 1);
        g_col[pos] = s;
    }
}

// ================= gather (fp16): agg[n] = mean_{s in nbrs(n)} h[s] =================
__device__ __forceinline__ void acc_row(float4& acc, uint2 v) {
    float2 f0 = __half22float2(*(__half2*)&v.x);
    float2 f1 = __half22float2(*(__half2*)&v.y);
    acc.x += f0.x; acc.y += f0.y; acc.z += f1.x; acc.w += f1.y;
}
__global__ __launch_bounds__(256) void gather_kernel(const __half* __restrict__ h,
                                                     __half* __restrict__ agg) {
    int warp = (blockIdx.x * 256 + threadIdx.x) >> 5;
    int lane = threadIdx.x & 31;
    if (warp >= N_NODES) return;
    int beg = __ldg(&g_rowptr[warp]);
    int end = __ldg(&g_rowptr[warp + 1]);
    const uint2* hp = (const uint2*)h;   // 32 uint2 per row (4 halfs each)
    float4 acc = make_float4(0.f, 0.f, 0.f, 0.f);
    int k = beg;
    for (; k + 4 <= end; k += 4) {
        int s0 = __ldg(&g_col[k]);
        int s1 = __ldg(&g_col[k + 1]);
        int s2 = __ldg(&g_col[k + 2]);
        int s3 = __ldg(&g_col[k + 3]);
        uint2 v0 = __ldg(hp + (size_t)s0 * 32 + lane);
        uint2 v1 = __ldg(hp + (size_t)s1 * 32 + lane);
        uint2 v2 = __ldg(hp + (size_t)s2 * 32 + lane);
        uint2 v3 = __ldg(hp + (size_t)s3 * 32 + lane);
        acc_row(acc, v0); acc_row(acc, v1); acc_row(acc, v2); acc_row(acc, v3);
    }
    for (; k < end; k++) {
        int s0 = __ldg(&g_col[k]);
        uint2 v0 = __ldg(hp + (size_t)s0 * 32 + lane);
        acc_row(acc, v0);
    }
    float sc = 1.0f / (float)max(end - beg, 1);
    uint2 o;
    o.x = cvt_f16x2(acc.x * sc, acc.y * sc);
    o.y = cvt_f16x2(acc.z * sc, acc.w * sc);
    ((uint2*)agg)[(size_t)warp * 32 + lane] = o;
}

// ================= mma.sync fp16 2-pass GEMM =================
// D[128x128] = sum_seg A_seg(fp16) @ (Whi_seg + Wlo_seg)^T + bias,
// optional LayerNorm + ReLU. 8 warps (4x2), each 32x64 output.
#define TSTRIDE 136                       // fp16 elems per smem row (padded)
#define TROWB (TSTRIDE * 2)               // 272 bytes
#define TILE_B (128 * TROWB)              // 34816 bytes per tile
#define OFF_A 0
#define OFF_WHI (OFF_A + TILE_B)
#define OFF_WLO (OFF_WHI + TILE_B)
#define GEMM_SMEM (3 * TILE_B)            // 104448

template <int NSEG, bool A_FP32, bool DO_LN, bool DO_RELU, bool OUT_HALF>
__global__ __launch_bounds__(256) void gemm_mma(
    const void* __restrict__ A0, const float* __restrict__ W0,
    const void* __restrict__ A1, const float* __restrict__ W1,
    const float* __restrict__ bias,
    const float* __restrict__ lng, const float* __restrict__ lnb,
    void* __restrict__ out, int nrows) {
    extern __shared__ __align__(16) char smem[];
    const uint32_t sb = smem_u32(smem);
    const int tid = threadIdx.x;
    const int lane = tid & 31;
    const int wid = tid >> 5;
    const int warpM = wid >> 1;           // 0..3 -> rows warpM*32
    const int warpN = wid & 1;            // 0..1 -> cols warpN*64
    const int row0 = blockIdx.x * 128;
    const int g = lane >> 2;
    const int t = lane & 3;

    float d[2][8][4];
#pragma unroll
    for (int mt = 0; mt < 2; mt++)
#pragma unroll
        for (int nt = 0; nt < 8; nt++)
#pragma unroll
            for (int e = 0; e < 4; e++) d[mt][nt][e] = 0.f;

    const int frag = lane >> 3;
    const uint32_t a_rel = (uint32_t)((warpM * 32 + (frag & 1) * 8 + (lane & 7)) * TROWB +
                                      (frag >> 1) * 16);
    const uint32_t b_rel = (uint32_t)((warpN * 64 + (frag >> 1) * 8 + (lane & 7)) * TROWB +
                                      (frag & 1) * 16);

#pragma unroll
    for (int seg = 0; seg < NSEG; seg++) {
        const void* A = (seg == 0) ? A0 : A1;
        const float* W = (seg == 0) ? W0 : W1;
        if (seg > 0) __syncthreads();

        // -------- fill: A (fp16 copy or fp32->fp16), W -> fp16 hi/lo --------
#pragma unroll 4
        for (int it = 0; it < 16; it++) {
            int r = wid + it * 8;        // 0..127
            uint32_t off = (uint32_t)(r * TROWB + lane * 8);
            int grow = row0 + r;

            uint2 aval = make_uint2(0u, 0u);
            if (grow < nrows) {
                if (A_FP32) {
                    float4 v = __ldg((const float4*)A + (size_t)grow * 32 + lane);
                    aval.x = cvt_f16x2(v.x, v.y);
                    aval.y = cvt_f16x2(v.z, v.w);
                } else {
                    aval = __ldg((const uint2*)A + (size_t)grow * 32 + lane);
                }
            }
            *(uint2*)(smem + OFF_A + off) = aval;

            float4 w = __ldg((const float4*)W + (size_t)r * 32 + lane);
            float gx = __half2float(__float2half_rn(w.x));
            float gy = __half2float(__float2half_rn(w.y));
            float gz = __half2float(__float2half_rn(w.z));
            float gw = __half2float(__float2half_rn(w.w));
            *(uint2*)(smem + OFF_WHI + off) =
                make_uint2(cvt_f16x2(gx, gy), cvt_f16x2(gz, gw));
            *(uint2*)(smem + OFF_WLO + off) =
                make_uint2(cvt_f16x2(w.x - gx, w.y - gy),
                           cvt_f16x2(w.z - gz, w.w - gw));
        }
        __syncthreads();

        // -------- compute: per k-step, A frags once, 2 W passes --------
#pragma unroll
        for (int ks = 0; ks < 8; ks++) {
            uint32_t af[2][4];
#pragma unroll
            for (int mt = 0; mt < 2; mt++)
                ldmx4(af[mt], sb + OFF_A + a_rel + mt * (16 * TROWB) + ks * 32);
#pragma unroll
            for (int pass = 0; pass < 2; pass++) {
                const uint32_t wbase =
                    sb + ((pass == 0) ? OFF_WHI : OFF_WLO) + b_rel + ks * 32;
                uint32_t bf[8][2];
#pragma unroll
                for (int ntp = 0; ntp < 4; ntp++) {
                    uint32_t r4[4];
                    ldmx4(r4, wbase + ntp * (16 * TROWB));
                    bf[2 * ntp][0] = r4[0]; bf[2 * ntp][1] = r4[1];
                    bf[2 * ntp + 1][0] = r4[2]; bf[2 * ntp + 1][1] = r4[3];
                }
#pragma unroll
                for (int mt = 0; mt < 2; mt++)
#pragma unroll
                    for (int nt = 0; nt < 8; nt++)
                        mma_fp16(d[mt][nt], af[mt], bf[nt]);
            }
        }
    }

    // ================= epilogue =================
#pragma unroll
    for (int nt = 0; nt < 8; nt++) {
        int C = warpN * 64 + nt * 8 + 2 * t;
        float2 bv = __ldg((const float2*)(bias + C));
#pragma unroll
        for (int mt = 0; mt < 2; mt++) {
            d[mt][nt][0] += bv.x; d[mt][nt][1] += bv.y;
            d[mt][nt][2] += bv.x; d[mt][nt][3] += bv.y;
        }
    }

    if (DO_LN) {
        __syncthreads();
        float* red_s = (float*)smem;        // [128][2]
        float* red_q = red_s + 256;
        float* s_mu = red_q + 256;
        float* s_rs = s_mu + 128;
#pragma unroll
        for (int mt = 0; mt < 2; mt++) {
#pragma unroll
            for (int rh = 0; rh < 2; rh++) {
                float s = 0.f, q = 0.f;
#pragma unroll
                for (int nt = 0; nt < 8; nt++) {
                    float v0 = d[mt][nt][2 * rh], v1 = d[mt][nt][2 * rh + 1];
                    s += v0 + v1;
                    q += v0 * v0 + v1 * v1;
                }
                s += __shfl_xor_sync(0xffffffff, s, 1);
                s += __shfl_xor_sync(0xffffffff, s, 2);
                q += __shfl_xor_sync(0xffffffff, q, 1);
                q += __shfl_xor_sync(0xffffffff, q, 2);
                if (t == 0) {
                    int r = warpM * 32 + mt * 16 + rh * 8 + g;
                    red_s[r * 2 + warpN] = s;
                    red_q[r * 2 + warpN] = q;
                }
            }
        }
        __syncthreads();
        if (tid < 128) {
            float st = red_s[tid * 2] + red_s[tid * 2 + 1];
            float qt = red_q[tid * 2] + red_q[tid * 2 + 1];
            float mu = st * (1.0f / 128.0f);
            float var = qt * (1.0f / 128.0f) - mu * mu;
            s_mu[tid] = mu;
            s_rs[tid] = rsqrtf(var + LN_EPS);
        }
        __syncthreads();
#pragma unroll
        for (int nt = 0; nt < 8; nt++) {
            int C = warpN * 64 + nt * 8 + 2 * t;
            float2 gv = __ldg((const float2*)(lng + C));
            float2 bv = __ldg((const float2*)(lnb + C));
#pragma unroll
            for (int mt = 0; mt < 2; mt++) {
#pragma unroll
                for (int rh = 0; rh < 2; rh++) {
                    int r = warpM * 32 + mt * 16 + rh * 8 + g;
                    float mu = s_mu[r], rs = s_rs[r];
                    d[mt][nt][2 * rh] = (d[mt][nt][2 * rh] - mu) * rs * gv.x + bv.x;
                    d[mt][nt][2 * rh + 1] =
                        (d[mt][nt][2 * rh + 1] - mu) * rs * gv.y + bv.y;
                }
            }
        }
    }

    if (DO_RELU) {
#pragma unroll
        for (int mt = 0; mt < 2; mt++)
#pragma unroll
            for (int nt = 0; nt < 8; nt++)
#pragma unroll
                for (int e = 0; e < 4; e++) d[mt][nt][e] = fmaxf(d[mt][nt][e], 0.f);
    }

    // store
#pragma unroll
    for (int mt = 0; mt < 2; mt++) {
#pragma unroll
        for (int rh = 0; rh < 2; rh++) {
            int R = row0 + warpM * 32 + mt * 16 + rh * 8 + g;
            if (R < nrows) {
                if (OUT_HALF) {
                    __half* pr = (__half*)out + (size_t)R * D + warpN * 64 + 2 * t;
#pragma unroll
                    for (int nt = 0; nt < 8; nt++)
                        *(uint32_t*)(pr + nt * 8) =
                            cvt_f16x2(d[mt][nt][2 * rh], d[mt][nt][2 * rh + 1]);
                } else {
                    float* pr = (float*)out + (size_t)R * D + warpN * 64 + 2 * t;
#pragma unroll
                    for (int nt = 0; nt < 8; nt++)
                        *(float2*)(pr + nt * 8) =
                            make_float2(d[mt][nt][2 * rh], d[mt][nt][2 * rh + 1]);
                }
            }
        }
    }
}

// ---------------- per-graph sum pool (batch sorted -> no atomics) ----------------
__global__ void graph_pool_kernel(const float* __restrict__ node,
                                  const int* __restrict__ batch,
                                  float* __restrict__ out) {
    int g = blockIdx.x;
    int c = threadIdx.x;  // 0..127
    int lo = 0, hi = N_NODES;
    while (lo < hi) {
        int mid = (lo + hi) >> 1;
        if (__ldg(batch + mid) < g) lo = mid + 1; else hi = mid;
    }
    int start = lo;
    hi = N_NODES;
    while (lo < hi) {
        int mid = (lo + hi) >> 1;
        if (__ldg(batch + mid) < g + 1) lo = mid + 1; else hi = mid;
    }
    int end = lo;
    float acc = 0.f;
    int n = start;
    for (; n + 4 <= end; n += 4) {
        acc += __ldg(node + (size_t)(n + 0) * D + c);
        acc += __ldg(node + (size_t)(n + 1) * D + c);
        acc += __ldg(node + (size_t)(n + 2) * D + c);
        acc += __ldg(node + (size_t)(n + 3) * D + c);
    }
    for (; n < end; n++) acc += __ldg(node + (size_t)n * D + c);
    out[(size_t)g * D + c] = acc;
}

// ---------------- launch ----------------
extern "C" void kernel_launch(void* const* d_in, const int* in_sizes, int n_in,
                              void* d_out, int out_size) {
    const float* x = (const float*)d_in[0];
    const int* ei = (const int*)d_in[1];
    const int* batch = (const int*)d_in[2];
    const float* fc_w = (const float*)d_in[3];
    const float* fc_b = (const float*)d_in[4];
    const float* Wl = (const float*)d_in[5];
    const float* bl = (const float*)d_in[6];
    const float* Wr = (const float*)d_in[7];
    const float* lng = (const float*)d_in[8];
    const float* lnb = (const float*)d_in[9];

    float* out_node = (float*)d_out;
    float* out_graph = out_node + (size_t)N_NODES * D;

    __half *h, *agg;
    cudaGetSymbolAddress((void**)&h, g_h);
    cudaGetSymbolAddress((void**)&agg, g_agg);

    cudaFuncSetAttribute(gemm_mma<1, true, false, true, true>,
                         cudaFuncAttributeMaxDynamicSharedMemorySize, GEMM_SMEM);
    cudaFuncSetAttribute(gemm_mma<2, false, true, true, true>,
                         cudaFuncAttributeMaxDynamicSharedMemorySize, GEMM_SMEM);
    cudaFuncSetAttribute(gemm_mma<2, false, false, false, false>,
                         cudaFuncAttributeMaxDynamicSharedMemorySize, GEMM_SMEM);

    // CSR build
    zero_cnt_kernel<<<(N_NODES + 255) / 256, 256>>>();
    count_kernel<<<(N_EDGES + 255) / 256, 256>>>(ei);
    scan1_kernel<<<N_SCAN_BLKS, SCAN_BLK>>>();
    scan2_kernel<<<1, 64>>>();
    scan3_kernel<<<(N_NODES + 255) / 256, 256>>>();
    fill_kernel<<<(N_EDGES + 255) / 256, 256>>>(ei);

    const int GBLK = (N_NODES + 127) / 128;  // 313

    // input projection + ReLU -> h (fp16)
    gemm_mma<1, true, false, true, true><<<GBLK, 256, GEMM_SMEM>>>(
        x, fc_w, nullptr, nullptr, fc_b, nullptr, nullptr, h, N_NODES);

    for (int i = 0; i < 3; i++) {
        gather_kernel<<<(N_NODES * 32 + 255) / 256, 256>>>(h, agg);
        if (i < 2) {
            gemm_mma<2, false, true, true, true><<<GBLK, 256, GEMM_SMEM>>>(
                agg, Wl + (size_t)i * D * D, h, Wr + (size_t)i * D * D,
                bl + (size_t)i * D, lng + (size_t)i * D, lnb + (size_t)i * D,
                h, N_NODES);
        } else {
            gemm_mma<2, false, false, false, false><<<GBLK, 256, GEMM_SMEM>>>(
                agg, Wl + (size_t)i * D * D, h, Wr + (size_t)i * D * D,
                bl + (size_t)i * D, nullptr, nullptr, out_node, N_NODES);
        }
    }

    graph_pool_kernel<<<N_GRAPHS, 128>>>(out_node, batch, out_graph);
}